// round 17
// baseline (speedup 1.0000x reference)
#include <cuda_runtime.h>
#include <cuda_fp16.h>
#include <math.h>
#include <stdint.h>

#define B_SZ 8192
#define T_SZ 8192
#define FD 768
#define PD 512
#define HD 1024
#define NE 4
#define CB 1024   // 2*P
#define NH 5376   // fused hidden: 4096 expert | 1024 ds | 256 router

typedef __half fp16;

// ---------------- scratch (device globals; no allocation allowed) ----------
__device__ float g_ds[B_SZ];
__device__ fp16  g_res[(size_t)B_SZ * FD];
__device__ fp16  g_hid[(size_t)B_SZ * NH];

__device__ __align__(256) fp16 g_txt_h[(size_t)B_SZ * FD];
__device__ __align__(256) fp16 g_img_h[(size_t)B_SZ * FD];
__device__ __align__(256) fp16 g_comb_h[(size_t)B_SZ * CB];
__device__ __align__(256) fp16 g_fused_h[(size_t)B_SZ * HD];
__device__ __align__(256) fp16 g_pred_h[(size_t)B_SZ * FD];
__device__ __align__(256) fp16 g_tgt_h[(size_t)T_SZ * FD];
__device__ __align__(256) fp16 g_Wt_h[(size_t)PD * FD];
__device__ __align__(256) fp16 g_Wi_h[(size_t)PD * FD];
__device__ __align__(256) fp16 g_bigW[(size_t)NH * CB];   // [expW | dsW1 | rtW1]
__device__ __align__(256) float g_bigB[NH];
__device__ __align__(256) fp16 g_outW_h[(size_t)FD * HD];

// ---------------- helpers ---------------------------------------------------
__device__ __forceinline__ float gelu_f(float x) {
    return 0.5f * x * (1.0f + erff(x * 0.70710678118654752440f));
}

__device__ __forceinline__ uint32_t smem_u32(const void* p) {
    uint32_t a;
    asm("{ .reg .u64 t; cvta.to.shared.u64 t, %1; cvt.u32.u64 %0, t; }" : "=r"(a) : "l"(p));
    return a;
}

__device__ __forceinline__ void cpasync16(uint32_t dst, const void* src) {
    asm volatile("cp.async.cg.shared.global [%0], [%1], 16;" :: "r"(dst), "l"(src));
}
__device__ __forceinline__ void cp_commit() {
    asm volatile("cp.async.commit_group;" ::: "memory");
}
__device__ __forceinline__ void cp_wait1() {
    asm volatile("cp.async.wait_group 1;" ::: "memory");
}
__device__ __forceinline__ void cp_wait0() {
    asm volatile("cp.async.wait_group 0;" ::: "memory");
}

__device__ __forceinline__ void ldsm4(uint32_t& r0, uint32_t& r1, uint32_t& r2, uint32_t& r3,
                                      uint32_t a) {
    asm volatile("ldmatrix.sync.aligned.m8n8.x4.shared.b16 {%0,%1,%2,%3}, [%4];"
                 : "=r"(r0), "=r"(r1), "=r"(r2), "=r"(r3) : "r"(a));
}

__device__ __forceinline__ void mma16816(float* c, const uint32_t* a, uint32_t b0, uint32_t b1) {
    asm volatile(
        "mma.sync.aligned.m16n8k16.row.col.f32.f16.f16.f32 "
        "{%0,%1,%2,%3}, {%4,%5,%6,%7}, {%8,%9}, {%0,%1,%2,%3};"
        : "+f"(c[0]), "+f"(c[1]), "+f"(c[2]), "+f"(c[3])
        : "r"(a[0]), "r"(a[1]), "r"(a[2]), "r"(a[3]), "r"(b0), "r"(b1));
}

__device__ __forceinline__ float2 h2f2(uint32_t h) {
    __half2 v = *(__half2*)&h;
    return __half22float2(v);
}

// ---------------- megacast: all f32->fp16 casts + bias concat ----------------
#define NB_TXT  3072
#define NB_IMG  3072
#define NB_WT   192
#define NB_WI   192
#define NB_EXPW 2048
#define NB_DSW  512
#define NB_RTW  128
#define NB_OUTW 384
#define NB_BIAS 3
#define NB_TOTAL (NB_TXT + NB_IMG + NB_WT + NB_WI + NB_EXPW + NB_DSW + NB_RTW + NB_OUTW + NB_BIAS)

__device__ __forceinline__ uint32_t pack2(float a, float b) {
    __half2 h = __floats2half2_rn(a, b);
    return *(uint32_t*)&h;
}

__device__ __forceinline__ void cast8(const float* __restrict__ x, fp16* __restrict__ h,
                                      size_t i) {
    float4 v0 = *(const float4*)(x + i);
    float4 v1 = *(const float4*)(x + i + 4);
    uint4 o;
    o.x = pack2(v0.x, v0.y); o.y = pack2(v0.z, v0.w);
    o.z = pack2(v1.x, v1.y); o.w = pack2(v1.z, v1.w);
    *(uint4*)(h + i) = o;
}

__global__ void megacast(const float* __restrict__ txt,  const float* __restrict__ img,
                         const float* __restrict__ Wt,   const float* __restrict__ Wi,
                         const float* __restrict__ expW, const float* __restrict__ dsW1,
                         const float* __restrict__ rtW1, const float* __restrict__ outW,
                         const float* __restrict__ expb, const float* __restrict__ dsb1,
                         const float* __restrict__ rtb1,
                         fp16* __restrict__ txh,  fp16* __restrict__ imh,
                         fp16* __restrict__ wth,  fp16* __restrict__ wih,
                         fp16* __restrict__ bigW, fp16* __restrict__ owh,
                         float* __restrict__ bigB)
{
    int b = blockIdx.x;
    if (b < NB_TXT) { cast8(txt, txh, ((size_t)b * 256 + threadIdx.x) * 8); return; }
    b -= NB_TXT;
    if (b < NB_IMG) { cast8(img, imh, ((size_t)b * 256 + threadIdx.x) * 8); return; }
    b -= NB_IMG;
    if (b < NB_WT)  { cast8(Wt, wth, ((size_t)b * 256 + threadIdx.x) * 8); return; }
    b -= NB_WT;
    if (b < NB_WI)  { cast8(Wi, wih, ((size_t)b * 256 + threadIdx.x) * 8); return; }
    b -= NB_WI;
    if (b < NB_EXPW) { cast8(expW, bigW, ((size_t)b * 256 + threadIdx.x) * 8); return; }
    b -= NB_EXPW;
    if (b < NB_DSW) {
        cast8(dsW1, bigW + (size_t)NE * HD * CB, ((size_t)b * 256 + threadIdx.x) * 8); return;
    }
    b -= NB_DSW;
    if (b < NB_RTW) {
        cast8(rtW1, bigW + (size_t)(NE * HD + HD) * CB, ((size_t)b * 256 + threadIdx.x) * 8); return;
    }
    b -= NB_RTW;
    if (b < NB_OUTW) { cast8(outW, owh, ((size_t)b * 256 + threadIdx.x) * 8); return; }
    b -= NB_OUTW;
    {
        int i = b * 2048 + threadIdx.x * 8;
#pragma unroll
        for (int q = 0; q < 8; q++) {
            int j = i + q;
            if (j < NH) {
                float v;
                if (j < NE * HD)           v = expb[j];
                else if (j < NE * HD + HD) v = dsb1[j - NE * HD];
                else                       v = rtb1[j - NE * HD - HD];
                bigB[j] = v;
            }
        }
    }
}

// ---------------- shared tile loader -----------------------------------------
#define STAGE 32768u

__device__ __forceinline__ void load_stage(
    uint32_t sb,
    const fp16* __restrict__ A, const fp16* __restrict__ B,
    int m0, int n0, int k0, int K, int t)
{
#pragma unroll
    for (int i = 0; i < 8; i++) {
        int id = t + (i << 7);
        int row = id >> 3, ch = id & 7;
        uint32_t off = (uint32_t)(row << 7) + (uint32_t)((ch ^ (row & 7)) << 4);
        cpasync16(sb + off, A + (size_t)(m0 + row) * K + k0 + (ch << 3));
    }
#pragma unroll
    for (int i = 0; i < 8; i++) {
        int id = t + (i << 7);
        int row = id >> 3, ch = id & 7;
        uint32_t off = (uint32_t)(row << 7) + (uint32_t)((ch ^ (row & 7)) << 4);
        cpasync16(sb + 16384 + off, B + (size_t)(n0 + row) * K + k0 + (ch << 3));
    }
}

// ---------------- fp16 HMMA GEMM, occ-2 / 3-stage (proven) -------------------
#define SMEM_G2 (3 * STAGE)

__global__ void __launch_bounds__(128, 2)
gemm_tc2(const fp16* __restrict__ A, const fp16* __restrict__ B,
         const float* __restrict__ bias,
         float* __restrict__ Cf, fp16* __restrict__ Ch,
         int K, int ldc, int act, const float* __restrict__ scale_ptr,
         const fp16* __restrict__ A2, const fp16* __restrict__ B2,
         const float* __restrict__ bias2, int colOff2)
{
    extern __shared__ __align__(128) char smem[];
    const uint32_t sb = smem_u32(smem);
    const int t = threadIdx.x;
    const int lane = t & 31, wid = t >> 5;
    const int wm = wid >> 1, wn = wid & 1;
    const int m0 = blockIdx.y * 128;
    const int n0 = blockIdx.x * 128;
    int coff = 0;
    if (blockIdx.z) { A = A2; B = B2; bias = bias2; coff = colOff2; }

    float acc[4][8][4];
#pragma unroll
    for (int i = 0; i < 4; i++)
#pragma unroll
        for (int j = 0; j < 8; j++)
#pragma unroll
            for (int q = 0; q < 4; q++) acc[i][j][q] = 0.f;

    const int lm = lane >> 3, lr8 = lane & 7;
    const int a_row  = wm * 64 + ((lm & 1) << 3) + lr8;
    const int a_choff = (lm >> 1);
    const int b_row  = wn * 64 + ((lm >> 1) << 3) + lr8;
    const int b_choff = (lm & 1);

    const int iters = K >> 6;

    load_stage(sb, A, B, m0, n0, 0, K, t);
    cp_commit();
    if (iters > 1) { load_stage(sb + STAGE, A, B, m0, n0, 64, K, t); cp_commit(); }

    for (int kt = 0; kt < iters; kt++) {
        if (kt + 1 < iters) cp_wait1();
        else cp_wait0();
        __syncthreads();
        if (kt + 2 < iters) {
            load_stage(sb + (uint32_t)((kt + 2) % 3) * STAGE, A, B, m0, n0, (kt + 2) << 6, K, t);
            cp_commit();
        }

        const uint32_t ss = sb + (uint32_t)(kt % 3) * STAGE;
#pragma unroll
        for (int kk = 0; kk < 4; kk++) {
            uint32_t Af[4][4], Bf[4][4];
            const int chA = 2 * kk + a_choff;
            const int chB = 2 * kk + b_choff;
#pragma unroll
            for (int mi = 0; mi < 4; mi++) {
                int row = a_row + mi * 16;
                uint32_t ad = ss + (row << 7) + (((chA ^ (row & 7))) << 4);
                ldsm4(Af[mi][0], Af[mi][1], Af[mi][2], Af[mi][3], ad);
            }
#pragma unroll
            for (int nj = 0; nj < 4; nj++) {
                int row = b_row + nj * 16;
                uint32_t ad = ss + 16384 + (row << 7) + (((chB ^ (row & 7))) << 4);
                ldsm4(Bf[nj][0], Bf[nj][1], Bf[nj][2], Bf[nj][3], ad);
            }
#pragma unroll
            for (int mi = 0; mi < 4; mi++) {
#pragma unroll
                for (int nj = 0; nj < 4; nj++) {
                    mma16816(acc[mi][nj * 2],     Af[mi], Bf[nj][0], Bf[nj][1]);
                    mma16816(acc[mi][nj * 2 + 1], Af[mi], Bf[nj][2], Bf[nj][3]);
                }
            }
        }
    }

    const float scale = scale_ptr ? expf(scale_ptr[0]) : 1.0f;
    const int lr = lane >> 2, lc = (lane & 3) * 2;
#pragma unroll
    for (int mi = 0; mi < 4; mi++) {
#pragma unroll
        for (int nj = 0; nj < 4; nj++) {
#pragma unroll
            for (int h = 0; h < 2; h++) {
                int col = n0 + wn * 64 + nj * 16 + h * 8 + lc;
                float bx = 0.f, by = 0.f;
                if (bias) { float2 bb = *(const float2*)(bias + col); bx = bb.x; by = bb.y; }
#pragma unroll
                for (int rh = 0; rh < 2; rh++) {
                    int row = m0 + wm * 64 + mi * 16 + rh * 8 + lr;
                    float v0 = acc[mi][nj * 2 + h][rh * 2 + 0] + bx;
                    float v1 = acc[mi][nj * 2 + h][rh * 2 + 1] + by;
                    if (act) { v0 = gelu_f(v0); v1 = gelu_f(v1); }
                    v0 *= scale; v1 *= scale;
                    size_t idx = (size_t)row * ldc + col + coff;
                    if (Cf) *(float2*)(Cf + idx) = make_float2(v0, v1);
                    if (Ch) *(__half2*)(Ch + idx) = __floats2half2_rn(v0, v1);
                }
            }
        }
    }
}

// ---------------- fp16 HMMA GEMM, occ-3 / 2-stage (logits experiment) --------
// B-fragment streaming trims live registers to fit 168/thread at 3 CTAs/SM.
#define SMEM_G3 (2 * STAGE)

__global__ void __launch_bounds__(128, 3)
gemm_tc3(const fp16* __restrict__ A, const fp16* __restrict__ B,
         float* __restrict__ Cf,
         int K, int ldc, const float* __restrict__ scale_ptr)
{
    extern __shared__ __align__(128) char smem[];
    const uint32_t sb = smem_u32(smem);
    const int t = threadIdx.x;
    const int lane = t & 31, wid = t >> 5;
    const int wm = wid >> 1, wn = wid & 1;
    const int m0 = blockIdx.y * 128;
    const int n0 = blockIdx.x * 128;

    float acc[4][8][4];
#pragma unroll
    for (int i = 0; i < 4; i++)
#pragma unroll
        for (int j = 0; j < 8; j++)
#pragma unroll
            for (int q = 0; q < 4; q++) acc[i][j][q] = 0.f;

    const int lm = lane >> 3, lr8 = lane & 7;
    const int a_row  = wm * 64 + ((lm & 1) << 3) + lr8;
    const int a_choff = (lm >> 1);
    const int b_row  = wn * 64 + ((lm >> 1) << 3) + lr8;
    const int b_choff = (lm & 1);

    const int iters = K >> 6;

    load_stage(sb, A, B, m0, n0, 0, K, t);
    cp_commit();

    for (int kt = 0; kt < iters; kt++) {
        cp_wait0();            // stage kt (the newest committed group) complete
        __syncthreads();       // visible to all; prev compute done -> other buffer free
        if (kt + 1 < iters) {
            load_stage(sb + (uint32_t)((kt + 1) & 1) * STAGE, A, B, m0, n0, (kt + 1) << 6, K, t);
            cp_commit();
        }

        const uint32_t ss = sb + (uint32_t)(kt & 1) * STAGE;
#pragma unroll
        for (int kk = 0; kk < 4; kk++) {
            uint32_t Af[4][4];
            const int chA = 2 * kk + a_choff;
            const int chB = 2 * kk + b_choff;
#pragma unroll
            for (int mi = 0; mi < 4; mi++) {
                int row = a_row + mi * 16;
                uint32_t ad = ss + (row << 7) + (((chA ^ (row & 7))) << 4);
                ldsm4(Af[mi][0], Af[mi][1], Af[mi][2], Af[mi][3], ad);
            }
            // stream B fragments: one ldsm -> 8 mma, keeps live regs low
#pragma unroll
            for (int nj = 0; nj < 4; nj++) {
                uint32_t Bf[4];
                int row = b_row + nj * 16;
                uint32_t ad = ss + 16384 + (row << 7) + (((chB ^ (row & 7))) << 4);
                ldsm4(Bf[0], Bf[1], Bf[2], Bf[3], ad);
#pragma unroll
                for (int mi = 0; mi < 4; mi++) {
                    mma16816(acc[mi][nj * 2],     Af[mi], Bf[0], Bf[1]);
                    mma16816(acc[mi][nj * 2 + 1], Af[mi], Bf[2], Bf[3]);
                }
            }
        }
        __syncthreads();       // all warps done with stage kt before it is reloaded
    }

    const float scale = scale_ptr ? expf(scale_ptr[0]) : 1.0f;
    const int lr = lane >> 2, lc = (lane & 3) * 2;
#pragma unroll
    for (int mi = 0; mi < 4; mi++) {
#pragma unroll
        for (int nj = 0; nj < 4; nj++) {
#pragma unroll
            for (int h = 0; h < 2; h++) {
                int col = n0 + wn * 64 + nj * 16 + h * 8 + lc;
#pragma unroll
                for (int rh = 0; rh < 2; rh++) {
                    int row = m0 + wm * 64 + mi * 16 + rh * 8 + lr;
                    float v0 = acc[mi][nj * 2 + h][rh * 2 + 0] * scale;
                    float v1 = acc[mi][nj * 2 + h][rh * 2 + 1] * scale;
                    *(float2*)(Cf + (size_t)row * ldc + col) = make_float2(v0, v1);
                }
            }
        }
    }
}

// ---------------- fused router softmax + ds sigmoid + expert mix -------------
__global__ void router_fuse(const fp16* __restrict__ hid,
                            const float* __restrict__ rtW2,
                            const float* __restrict__ rtb2,
                            const float* __restrict__ dsW2,
                            const float* __restrict__ dsb2,
                            fp16* __restrict__ fusedh,
                            float* __restrict__ ds_buf,
                            float* __restrict__ out_ds,
                            float* __restrict__ out_probs)
{
    int b = blockIdx.x;
    int t = threadIdx.x;           // 256
    int lane = t & 31, w = t >> 5; // 8 warps
    const fp16* row = hid + (size_t)b * NH;

    __shared__ float sl[4], dsp[4], sprob[4];

    if (w < 4) {
        const fp16* x = row + NE * HD + HD;
        const float* wr = rtW2 + (size_t)w * 256;
        float s = 0.f;
#pragma unroll
        for (int i = lane; i < 128; i += 32) {
            float2 xv = h2f2(*(const uint32_t*)(x + 2 * i));
            float2 wv = *(const float2*)(wr + 2 * i);
            s += xv.x * wv.x + xv.y * wv.y;
        }
#pragma unroll
        for (int o = 16; o; o >>= 1) s += __shfl_xor_sync(0xffffffffu, s, o);
        if (lane == 0) sl[w] = s + rtb2[w];
    } else {
        int seg = w - 4;
        const fp16* xr = row + NE * HD + seg * 256;
        const float* wd = dsW2 + seg * 256;
        float s = 0.f;
#pragma unroll
        for (int i = lane; i < 128; i += 32) {
            float2 xv = h2f2(*(const uint32_t*)(xr + 2 * i));
            float2 wv = *(const float2*)(wd + 2 * i);
            s += xv.x * wv.x + xv.y * wv.y;
        }
#pragma unroll
        for (int o = 16; o; o >>= 1) s += __shfl_xor_sync(0xffffffffu, s, o);
        if (lane == 0) dsp[seg] = s;
    }
    __syncthreads();

    if (t == 0) {
        float m = fmaxf(fmaxf(sl[0], sl[1]), fmaxf(sl[2], sl[3]));
        float e[4]; float sum = 0.f;
#pragma unroll
        for (int i = 0; i < 4; i++) { e[i] = expf(sl[i] - m); sum += e[i]; }
        float inv = 1.f / sum;
        float4 p = make_float4(e[0] * inv, e[1] * inv, e[2] * inv, e[3] * inv);
        sprob[0] = p.x; sprob[1] = p.y; sprob[2] = p.z; sprob[3] = p.w;
        *(float4*)(out_probs + (size_t)b * 4) = p;
    }
    if (t == 32) {
        float d = 1.f / (1.f + expf(-(dsp[0] + dsp[1] + dsp[2] + dsp[3] + dsb2[0])));
        ds_buf[b] = d;
        out_ds[b] = d;
    }
    __syncthreads();

    float p0 = sprob[0], p1 = sprob[1], p2 = sprob[2], p3 = sprob[3];
    {
        int h = t * 4;
        uint2 e0 = *(const uint2*)(row + h);
        uint2 e1 = *(const uint2*)(row + HD + h);
        uint2 e2 = *(const uint2*)(row + 2 * HD + h);
        uint2 e3 = *(const uint2*)(row + 3 * HD + h);
        float2 a0 = h2f2(e0.x), b0 = h2f2(e0.y);
        float2 a1 = h2f2(e1.x), b1 = h2f2(e1.y);
        float2 a2 = h2f2(e2.x), b2 = h2f2(e2.y);
        float2 a3 = h2f2(e3.x), b3 = h2f2(e3.y);
        float v0 = p0 * a0.x + p1 * a1.x + p2 * a2.x + p3 * a3.x;
        float v1 = p0 * a0.y + p1 * a1.y + p2 * a2.y + p3 * a3.y;
        float v2 = p0 * b0.x + p1 * b1.x + p2 * b2.x + p3 * b3.x;
        float v3 = p0 * b0.y + p1 * b1.y + p2 * b2.y + p3 * b3.y;
        uint2 o;
        o.x = pack2(v0, v1);
        o.y = pack2(v2, v3);
        *(uint2*)(fusedh + (size_t)b * HD + h) = o;
    }
}

// ---------------- mix + L2 normalize, vectorized -----------------------------
__global__ void norm_kernel(const fp16* __restrict__ res,
                            const float* __restrict__ text,
                            const float* __restrict__ img,
                            const float* __restrict__ ds_buf,
                            const float* __restrict__ target,
                            fp16* __restrict__ predh,
                            fp16* __restrict__ tgth)
{
    int r = blockIdx.x;
    int t = threadIdx.x;  // 256; threads 0..191 active (192*4 = 768)
    float o[4] = {0.f, 0.f, 0.f, 0.f};
    fp16* dh;
    size_t base;
    bool active = t < 192;
    int j = t * 4;
    if (r < B_SZ) {
        float d = ds_buf[r];
        base = (size_t)r * FD;
        if (active) {
            float4 tx = *(const float4*)(text + base + j);
            float4 im = *(const float4*)(img + base + j);
            uint2 rs = *(const uint2*)(res + base + j);
            float2 r01 = h2f2(rs.x), r23 = h2f2(rs.y);
            o[0] = d * tx.x + (1.0f - d) * im.x + r01.x;
            o[1] = d * tx.y + (1.0f - d) * im.y + r01.y;
            o[2] = d * tx.z + (1.0f - d) * im.z + r23.x;
            o[3] = d * tx.w + (1.0f - d) * im.w + r23.y;
        }
        dh = predh;
    } else {
        base = (size_t)(r - B_SZ) * FD;
        if (active) {
            float4 tg = *(const float4*)(target + base + j);
            o[0] = tg.x; o[1] = tg.y; o[2] = tg.z; o[3] = tg.w;
        }
        dh = tgth;
    }
    float s = o[0] * o[0] + o[1] * o[1] + o[2] * o[2] + o[3] * o[3];
    __shared__ float red[256];
    red[t] = s;
    __syncthreads();
    for (int off = 128; off; off >>= 1) {
        if (t < off) red[t] += red[t + off];
        __syncthreads();
    }
    __shared__ float inv_s;
    if (t == 0) inv_s = 1.0f / fmaxf(sqrtf(red[0]), 1e-12f);
    __syncthreads();
    float inv = inv_s;
    if (active) {
        uint2 w;
        w.x = pack2(o[0] * inv, o[1] * inv);
        w.y = pack2(o[2] * inv, o[3] * inv);
        *(uint2*)(dh + base + j) = w;
    }
}

// ---------------- launch -----------------------------------------------------
#define SYM(var, sym) cudaGetSymbolAddress((void**)&var, sym)

extern "C" void kernel_launch(void* const* d_in, const int* in_sizes, int n_in,
                              void* d_out, int out_size)
{
    const float* img  = (const float*)d_in[0];
    const float* txt  = (const float*)d_in[1];
    const float* tgt  = (const float*)d_in[2];
    const float* Wt   = (const float*)d_in[3];
    const float* bt   = (const float*)d_in[4];
    const float* Wi   = (const float*)d_in[5];
    const float* bi   = (const float*)d_in[6];
    const float* dsW1 = (const float*)d_in[7];
    const float* dsb1 = (const float*)d_in[8];
    const float* dsW2 = (const float*)d_in[9];
    const float* dsb2 = (const float*)d_in[10];
    const float* expW = (const float*)d_in[11];
    const float* expb = (const float*)d_in[12];
    const float* rtW1 = (const float*)d_in[13];
    const float* rtb1 = (const float*)d_in[14];
    const float* rtW2 = (const float*)d_in[15];
    const float* rtb2 = (const float*)d_in[16];
    const float* outW = (const float*)d_in[17];
    const float* outb = (const float*)d_in[18];
    const float* lsc  = (const float*)d_in[19];

    float *ds, *bigB;
    fp16 *hid, *resh;
    SYM(ds, g_ds); SYM(hid, g_hid); SYM(bigB, g_bigB); SYM(resh, g_res);

    fp16 *txh, *imh, *cbh, *fuh, *prh, *tgh;
    fp16 *wth, *wih, *bigW, *owh;
    SYM(txh, g_txt_h); SYM(imh, g_img_h);
    SYM(cbh, g_comb_h); SYM(fuh, g_fused_h);
    SYM(prh, g_pred_h); SYM(tgh, g_tgt_h);
    SYM(wth, g_Wt_h); SYM(wih, g_Wi_h); SYM(bigW, g_bigW); SYM(owh, g_outW_h);

    float* out_logits = (float*)d_out;
    float* out_ds     = out_logits + (size_t)B_SZ * T_SZ;
    float* out_probs  = out_ds + B_SZ;

    cudaFuncSetAttribute(gemm_tc2, cudaFuncAttributeMaxDynamicSharedMemorySize, SMEM_G2);
    cudaFuncSetAttribute(gemm_tc3, cudaFuncAttributeMaxDynamicSharedMemorySize, SMEM_G3);

    // (1) all casts + bias concat in one launch
    megacast<<<NB_TOTAL, 256>>>(txt, img, Wt, Wi, expW, dsW1, rtW1, outW,
                                expb, dsb1, rtb1,
                                txh, imh, wth, wih, bigW, owh, bigB);

    dim3 blk(128);
    // (2) both projections in ONE launch
    gemm_tc2<<<dim3(PD / 128, B_SZ / 128, 2), blk, SMEM_G2>>>(
        txh, wth, bt, nullptr, cbh, FD, CB, 1, nullptr, imh, wih, bi, PD);

    // (3) fused hidden GEMM: [B, 5376]
    gemm_tc2<<<dim3(NH / 128, B_SZ / 128, 1), blk, SMEM_G2>>>(
        cbh, bigW, bigB, nullptr, hid, CB, NH, 1, nullptr, nullptr, nullptr, nullptr, 0);

    // (4) router softmax + ds sigmoid + expert mix
    router_fuse<<<B_SZ, 256>>>(hid, rtW2, rtb2, dsW2, dsb2, fuh, ds, out_ds, out_probs);

    // (5) residual [B, 768] -> fp16
    gemm_tc2<<<dim3(FD / 128, B_SZ / 128, 1), blk, SMEM_G2>>>(
        fuh, owh, outb, nullptr, resh, HD, FD, 0, nullptr, nullptr, nullptr, nullptr, 0);

    // (6) mix + normalize -> pred/tgt fp16
    norm_kernel<<<B_SZ + T_SZ, 256>>>(resh, txt, img, ds, tgt, prh, tgh);

    // (7) logits: occ-3 experimental GEMM
    gemm_tc3<<<dim3(T_SZ / 128, B_SZ / 128, 1), blk, SMEM_G3>>>(
        prh, tgh, out_logits, FD, T_SZ, lsc);
}